// round 1
// baseline (speedup 1.0000x reference)
#include <cuda_runtime.h>
#include <math.h>

// Problem constants (fixed shapes)
#define B_  4
#define T_  2048
#define D_  2048
#define H_  16
#define HD_ 128
#define NTOK_ (B_*T_)                 // 8192
#define SCALE_ 0.08838834764831845f   // 1/sqrt(128)

// Scratch (allocation-free rule: __device__ globals). 4 x 64MB.
__device__ float g_q[NTOK_*(size_t)D_];
__device__ float g_k[NTOK_*(size_t)D_];
__device__ float g_v[NTOK_*(size_t)D_];
__device__ float g_y[NTOK_*(size_t)D_];

// ---------------------------------------------------------------------------
// GEMM: C[M,N] = A[M,K] @ W[N,K]^T   (both row-major, K contiguous)
// 128x128 tile, BK=8, 256 threads, 8x8 micro-tile.
// Thread columns are {4*tn .. 4*tn+3} and {64+4*tn .. 64+4*tn+3} so Ws float4
// reads are bank-phase conflict-free.
// ---------------------------------------------------------------------------
__global__ __launch_bounds__(256, 2)
void sgemm_nt(const float* __restrict__ A, const float* __restrict__ W,
              float* __restrict__ C, int M, int N, int K)
{
    __shared__ float As[8][128];
    __shared__ float Ws[8][128];
    const int m0 = blockIdx.y * 128;
    const int n0 = blockIdx.x * 128;
    const int tid = threadIdx.x;
    const int tm = tid >> 4;        // 0..15
    const int tn = tid & 15;        // 0..15
    const int lr = tid >> 1;        // 0..127 tile row for loading
    const int lu = (tid & 1) << 2;  // 0 or 4 within k-chunk

    const float* Ap = A + (size_t)(m0 + lr) * K + lu;
    const float* Wp = W + (size_t)(n0 + lr) * K + lu;

    float acc[8][8];
#pragma unroll
    for (int i = 0; i < 8; i++)
#pragma unroll
        for (int j = 0; j < 8; j++) acc[i][j] = 0.f;

    for (int k0 = 0; k0 < K; k0 += 8) {
        float4 a = *(const float4*)(Ap + k0);
        float4 w = *(const float4*)(Wp + k0);
        __syncthreads();
        As[lu+0][lr] = a.x; As[lu+1][lr] = a.y; As[lu+2][lr] = a.z; As[lu+3][lr] = a.w;
        Ws[lu+0][lr] = w.x; Ws[lu+1][lr] = w.y; Ws[lu+2][lr] = w.z; Ws[lu+3][lr] = w.w;
        __syncthreads();
#pragma unroll
        for (int kk = 0; kk < 8; kk++) {
            float ra[8], rw[8];
            *(float4*)(ra)     = *(const float4*)&As[kk][tm*8];
            *(float4*)(ra + 4) = *(const float4*)&As[kk][tm*8 + 4];
            *(float4*)(rw)     = *(const float4*)&Ws[kk][tn*4];
            *(float4*)(rw + 4) = *(const float4*)&Ws[kk][(tn+16)*4];
#pragma unroll
            for (int i = 0; i < 8; i++)
#pragma unroll
                for (int j = 0; j < 8; j++)
                    acc[i][j] = fmaf(ra[i], rw[j], acc[i][j]);
        }
    }
#pragma unroll
    for (int i = 0; i < 8; i++) {
        float* Cp = C + (size_t)(m0 + tm*8 + i) * N + n0;
        *(float4*)(Cp + tn*4)        = make_float4(acc[i][0], acc[i][1], acc[i][2], acc[i][3]);
        *(float4*)(Cp + (tn+16)*4)   = make_float4(acc[i][4], acc[i][5], acc[i][6], acc[i][7]);
    }
}

// ---------------------------------------------------------------------------
// RoPE, in-place on q and k in [B,T,H*hd] layout. One thread per (b,t,h,i<64).
// ---------------------------------------------------------------------------
__global__ void rope_kernel(float* __restrict__ q, float* __restrict__ k)
{
    int idx = blockIdx.x * blockDim.x + threadIdx.x;
    if (idx >= B_*T_*H_*64) return;
    int i = idx & 63;
    int h = (idx >> 6) & (H_ - 1);
    int t = (idx >> 10) & (T_ - 1);
    int b = idx >> 21;

    float ex  = (float)(2*i) * (1.0f / (float)HD_);
    float inv = powf(10000.0f, -ex);
    float ang = (float)t * inv;
    float c = cosf(ang), s = sinf(ang);

    size_t base = ((size_t)(b*T_ + t)) * D_ + h*HD_ + i;
    float q1 = q[base], q2 = q[base + 64];
    q[base]      = q1*c - q2*s;
    q[base + 64] = q2*c + q1*s;
    float k1 = k[base], k2 = k[base + 64];
    k[base]      = k1*c - k2*s;
    k[base + 64] = k2*c + k1*s;
}

// ---------------------------------------------------------------------------
// Flash attention, fp32, causal. Block = 256 threads handles one
// (b, h, 64-row q tile). Bc = 64. q/k/v in [B,T,H*hd] layout (head stride 128).
//
// Smem swizzle: float4-chunk index c4 (0..31) xored with a 5-bit rotation of
// the row -> conflict-free for both coalesced stores (same row/warp) and the
// strided per-(i/j) reads in the S phase.
// ---------------------------------------------------------------------------
__device__ __forceinline__ int rot5(int r) {
    return ((r >> 2) & 7) | ((r & 3) << 3);
}
__device__ __forceinline__ int swz(int r, int c4) {
    return (r << 5) | (c4 ^ rot5(r));
}

#define ATT_SMEM_FLOATS (3*64*32*4 + 64*65)   // Q4,K4,V4 (as float4) + Ps
#define ATT_SMEM_BYTES  (ATT_SMEM_FLOATS * 4)

__global__ __launch_bounds__(256)
void attn_kernel(const float* __restrict__ q, const float* __restrict__ k,
                 const float* __restrict__ v, float* __restrict__ y)
{
    extern __shared__ float sm[];
    float4* Q4 = (float4*)sm;
    float4* K4 = Q4 + 64*32;
    float4* V4 = K4 + 64*32;
    float*  Ps = (float*)(V4 + 64*32);   // [64][65]

    const int qt = blockIdx.x;           // q tile (64 rows)
    const int h  = blockIdx.y;
    const int b  = blockIdx.z;
    const int q0 = qt * 64;
    const int tid = threadIdx.x;
    const int tm = tid >> 4;             // 0..15
    const int tn = tid & 15;             // 0..15

    const size_t headbase = ((size_t)b * T_) * D_ + (size_t)h * HD_;
    const float* qb = q + headbase + (size_t)q0 * D_;

    // Load + scale Q tile (64 x 128) into swizzled smem
    for (int f = tid; f < 2048; f += 256) {
        int r = f >> 5, c4 = f & 31;
        float4 t4 = *(const float4*)(qb + (size_t)r * D_ + (c4 << 2));
        t4.x *= SCALE_; t4.y *= SCALE_; t4.z *= SCALE_; t4.w *= SCALE_;
        Q4[swz(r, c4)] = t4;
    }

    float4 oA[4], oB[4];
    float mrow[4], lrow[4];
#pragma unroll
    for (int i = 0; i < 4; i++) {
        oA[i] = make_float4(0.f, 0.f, 0.f, 0.f);
        oB[i] = make_float4(0.f, 0.f, 0.f, 0.f);
        mrow[i] = -1e30f;
        lrow[i] = 0.f;
    }

    int qoff[4], qmsk[4], koff[4], kmsk[4];
#pragma unroll
    for (int i = 0; i < 4; i++) {
        int r = tm*4 + i; qoff[i] = r << 5; qmsk[i] = rot5(r);
        int c = tn*4 + i; koff[i] = c << 5; kmsk[i] = rot5(c);
    }

    for (int jt = 0; jt <= qt; jt++) {
        const int k0 = jt * 64;
        __syncthreads();   // all threads done with Ks/Vs/Ps from prev iter
        const float* kb = k + headbase + (size_t)k0 * D_;
        const float* vb = v + headbase + (size_t)k0 * D_;
        for (int f = tid; f < 2048; f += 256) {
            int r = f >> 5, c4 = f & 31;
            K4[swz(r, c4)]   = *(const float4*)(kb + (size_t)r * D_ + (c4 << 2));
            V4[(r << 5) | c4] = *(const float4*)(vb + (size_t)r * D_ + (c4 << 2));
        }
        __syncthreads();

        // S = (Q*scale) @ K^T   : 4x4 micro per thread
        float s[4][4];
#pragma unroll
        for (int i = 0; i < 4; i++)
#pragma unroll
            for (int j = 0; j < 4; j++) s[i][j] = 0.f;

#pragma unroll 2
        for (int d4 = 0; d4 < 32; d4++) {
            float4 qv[4], kv[4];
#pragma unroll
            for (int i = 0; i < 4; i++) qv[i] = Q4[qoff[i] | (d4 ^ qmsk[i])];
#pragma unroll
            for (int j = 0; j < 4; j++) kv[j] = K4[koff[j] | (d4 ^ kmsk[j])];
#pragma unroll
            for (int i = 0; i < 4; i++)
#pragma unroll
                for (int j = 0; j < 4; j++) {
                    s[i][j] = fmaf(qv[i].x, kv[j].x, s[i][j]);
                    s[i][j] = fmaf(qv[i].y, kv[j].y, s[i][j]);
                    s[i][j] = fmaf(qv[i].z, kv[j].z, s[i][j]);
                    s[i][j] = fmaf(qv[i].w, kv[j].w, s[i][j]);
                }
        }

        if (jt == qt) {   // causal mask within diagonal tile
#pragma unroll
            for (int i = 0; i < 4; i++)
#pragma unroll
                for (int j = 0; j < 4; j++)
                    if (tn*4 + j > tm*4 + i) s[i][j] = -1e30f;
        }

        // Online softmax (per-row stats replicated over the 16 threads of a row)
#pragma unroll
        for (int i = 0; i < 4; i++) {
            float rm = fmaxf(fmaxf(s[i][0], s[i][1]), fmaxf(s[i][2], s[i][3]));
#pragma unroll
            for (int o = 1; o < 16; o <<= 1)
                rm = fmaxf(rm, __shfl_xor_sync(0xffffffffu, rm, o));
            float mn  = fmaxf(mrow[i], rm);
            float fct = __expf(mrow[i] - mn);
            mrow[i] = mn;
            float rs = 0.f;
#pragma unroll
            for (int j = 0; j < 4; j++) {
                float p = __expf(s[i][j] - mn);
                s[i][j] = p;
                rs += p;
            }
#pragma unroll
            for (int o = 1; o < 16; o <<= 1)
                rs += __shfl_xor_sync(0xffffffffu, rs, o);
            lrow[i] = lrow[i] * fct + rs;
            oA[i].x *= fct; oA[i].y *= fct; oA[i].z *= fct; oA[i].w *= fct;
            oB[i].x *= fct; oB[i].y *= fct; oB[i].z *= fct; oB[i].w *= fct;
            Ps[(tm*4 + i)*65 + tn*4 + 0] = s[i][0];
            Ps[(tm*4 + i)*65 + tn*4 + 1] = s[i][1];
            Ps[(tm*4 + i)*65 + tn*4 + 2] = s[i][2];
            Ps[(tm*4 + i)*65 + tn*4 + 3] = s[i][3];
        }
        __syncthreads();

        // O += P @ V : thread covers cols {4*tn..+3} and {64+4*tn..+3}
#pragma unroll 2
        for (int kk = 0; kk < 64; kk++) {
            float4 va  = V4[(kk << 5) | tn];
            float4 vb4 = V4[(kk << 5) | (tn + 16)];
#pragma unroll
            for (int i = 0; i < 4; i++) {
                float p = Ps[(tm*4 + i)*65 + kk];
                oA[i].x = fmaf(p, va.x,  oA[i].x);
                oA[i].y = fmaf(p, va.y,  oA[i].y);
                oA[i].z = fmaf(p, va.z,  oA[i].z);
                oA[i].w = fmaf(p, va.w,  oA[i].w);
                oB[i].x = fmaf(p, vb4.x, oB[i].x);
                oB[i].y = fmaf(p, vb4.y, oB[i].y);
                oB[i].z = fmaf(p, vb4.z, oB[i].z);
                oB[i].w = fmaf(p, vb4.w, oB[i].w);
            }
        }
    }

    // Normalize and write y
    float* yb = y + headbase + (size_t)q0 * D_;
#pragma unroll
    for (int i = 0; i < 4; i++) {
        float inv = 1.0f / lrow[i];
        float4 ra = oA[i]; ra.x *= inv; ra.y *= inv; ra.z *= inv; ra.w *= inv;
        float4 rb = oB[i]; rb.x *= inv; rb.y *= inv; rb.z *= inv; rb.w *= inv;
        *(float4*)(yb + (size_t)(tm*4 + i) * D_ + (tn << 2))        = ra;
        *(float4*)(yb + (size_t)(tm*4 + i) * D_ + ((tn + 16) << 2)) = rb;
    }
}

// ---------------------------------------------------------------------------
extern "C" void kernel_launch(void* const* d_in, const int* in_sizes, int n_in,
                              void* d_out, int out_size)
{
    const float* x  = (const float*)d_in[0];
    const float* wq = (const float*)d_in[1];
    const float* wk = (const float*)d_in[2];
    const float* wv = (const float*)d_in[3];
    const float* wo = (const float*)d_in[4];
    float* out = (float*)d_out;

    float *q, *k, *v, *y;
    cudaGetSymbolAddress((void**)&q, g_q);
    cudaGetSymbolAddress((void**)&k, g_k);
    cudaGetSymbolAddress((void**)&v, g_v);
    cudaGetSymbolAddress((void**)&y, g_y);

    cudaFuncSetAttribute(attn_kernel,
                         cudaFuncAttributeMaxDynamicSharedMemorySize,
                         ATT_SMEM_BYTES);

    dim3 gproj(D_ / 128, NTOK_ / 128);   // (16, 64)
    sgemm_nt<<<gproj, 256>>>(x, wq, q, NTOK_, D_, D_);
    sgemm_nt<<<gproj, 256>>>(x, wk, k, NTOK_, D_, D_);
    sgemm_nt<<<gproj, 256>>>(x, wv, v, NTOK_, D_, D_);

    int nrope = B_*T_*H_*64;
    rope_kernel<<<(nrope + 255) / 256, 256>>>(q, k);

    dim3 gattn(T_ / 64, H_, B_);         // (32, 16, 4)
    attn_kernel<<<gattn, 256, ATT_SMEM_BYTES>>>(q, k, v, y);

    sgemm_nt<<<gproj, 256>>>(y, wo, out, NTOK_, D_, D_);
}

// round 3
// speedup vs baseline: 2.0675x; 2.0675x over previous
#include <cuda_runtime.h>
#include <math.h>
#include <stdint.h>

// Problem constants (fixed shapes)
#define B_  4
#define T_  2048
#define D_  2048
#define H_  16
#define HD_ 128
#define NTOK_ (B_*T_)                 // 8192
#define SCALE_ 0.08838834764831845f   // 1/sqrt(128)

// Scratch (allocation-free rule: __device__ globals). 4 x 64MB.
__device__ float g_q[NTOK_*(size_t)D_];
__device__ float g_k[NTOK_*(size_t)D_];
__device__ float g_v[NTOK_*(size_t)D_];
__device__ float g_y[NTOK_*(size_t)D_];

// ===========================================================================
// Helpers
// ===========================================================================
__device__ __forceinline__ uint32_t smem_u32(const void* p) {
    uint32_t a;
    asm("{ .reg .u64 t; cvta.to.shared.u64 t, %1; cvt.u32.u64 %0, t; }"
        : "=r"(a) : "l"(p));
    return a;
}
__device__ __forceinline__ void cp16(uint32_t saddr, const void* gaddr) {
    asm volatile("cp.async.cg.shared.global [%0], [%1], 16;"
                 :: "r"(saddr), "l"(gaddr) : "memory");
}
#define CP_COMMIT() asm volatile("cp.async.commit_group;" ::: "memory")
#define CP_WAIT0()  asm volatile("cp.async.wait_group 0;" ::: "memory")

__device__ __forceinline__ uint32_t f2tf32(float f) {
    uint32_t u;
    asm("cvt.rna.tf32.f32 %0, %1;" : "=r"(u) : "f"(f));
    return u;
}
__device__ __forceinline__ void mma_tf32(float c[4], uint32_t a0, uint32_t a1,
                                         uint32_t a2, uint32_t a3,
                                         uint32_t b0, uint32_t b1) {
    asm volatile(
        "mma.sync.aligned.m16n8k8.row.col.f32.tf32.tf32.f32 "
        "{%0,%1,%2,%3}, {%4,%5,%6,%7}, {%8,%9}, {%0,%1,%2,%3};"
        : "+f"(c[0]), "+f"(c[1]), "+f"(c[2]), "+f"(c[3])
        : "r"(a0), "r"(a1), "r"(a2), "r"(a3), "r"(b0), "r"(b1));
}

// ===========================================================================
// tf32 mma.sync GEMM: C[M,N] = A[M,K] @ W[N,K]^T  (both row-major).
// CTA 128x128, BK=32, 256 threads = 8 warps (2M x 4N), warp tile 64x32.
// smem pitch 36 floats -> conflict-free fragment LDS ((4g+tg) bank pattern).
// cp.async double-buffered pipeline.
// ===========================================================================
#define BK_      32
#define PITCH_   36
#define STAGE_F  (128 * PITCH_)               // floats per stage per operand
#define GEMM_SMEM_BYTES (4 * STAGE_F * 4)     // 2 stages x (A+B) = 73728 B

__global__ __launch_bounds__(256)
void mma_gemm_nt(const float* __restrict__ A, const float* __restrict__ W,
                 float* __restrict__ C, int M, int N, int K)
{
    extern __shared__ float smf[];
    float* Asm = smf;                  // [2][128][36]
    float* Bsm = smf + 2 * STAGE_F;    // [2][128][36]

    const int tid  = threadIdx.x;
    const int wid  = tid >> 5;
    const int lane = tid & 31;
    const int g    = lane >> 2;        // 0..7
    const int tg   = lane & 3;         // 0..3
    const int warpM = (wid & 1) * 64;
    const int warpN = (wid >> 1) * 32;
    const int m0 = blockIdx.y * 128;
    const int n0 = blockIdx.x * 128;

    // Loader slots: f = tid + u*256; r = f>>3 (row 0..127), c4 = f&7 (16B chunk)
    const int lr = tid >> 3;
    const int lc4 = tid & 7;
    const uint32_t sA_base = smem_u32(Asm);
    const uint32_t sB_base = smem_u32(Bsm);

    float acc[4][4][4];
#pragma unroll
    for (int i = 0; i < 4; i++)
#pragma unroll
        for (int j = 0; j < 4; j++)
#pragma unroll
            for (int c = 0; c < 4; c++) acc[i][j][c] = 0.f;

    const int niter = K / BK_;

    // ---- issue loads for chunk 'ck' into stage 's' ----
    auto issue = [&](int ck, int s) {
        const float* Ab = A + (size_t)m0 * K + ck * BK_;
        const float* Wb = W + (size_t)n0 * K + ck * BK_;
        const uint32_t so = (uint32_t)(s * STAGE_F * 4);
#pragma unroll
        for (int u = 0; u < 4; u++) {
            int r = lr + u * 32;
            cp16(sA_base + so + (uint32_t)(r * PITCH_ + lc4 * 4) * 4,
                 Ab + (size_t)r * K + lc4 * 4);
        }
#pragma unroll
        for (int u = 0; u < 4; u++) {
            int r = lr + u * 32;
            cp16(sB_base + so + (uint32_t)(r * PITCH_ + lc4 * 4) * 4,
                 Wb + (size_t)r * K + lc4 * 4);
        }
    };

    issue(0, 0);
    CP_COMMIT();
    CP_WAIT0();
    __syncthreads();

    for (int it = 0; it < niter; it++) {
        const int cur = it & 1;
        if (it + 1 < niter) {
            issue(it + 1, cur ^ 1);
            CP_COMMIT();
        }

        const float* As = Asm + cur * STAGE_F + (warpM + g) * PITCH_;
        const float* Bs = Bsm + cur * STAGE_F + (warpN + g) * PITCH_;
#pragma unroll
        for (int ks = 0; ks < 4; ks++) {
            const int kc = ks * 8 + tg;
            uint32_t af[4][4], bf[4][2];
#pragma unroll
            for (int mi = 0; mi < 4; mi++) {
                const float* p = As + mi * 16 * PITCH_ + kc;
                af[mi][0] = f2tf32(p[0]);
                af[mi][1] = f2tf32(p[8 * PITCH_]);
                af[mi][2] = f2tf32(p[4]);
                af[mi][3] = f2tf32(p[8 * PITCH_ + 4]);
            }
#pragma unroll
            for (int nj = 0; nj < 4; nj++) {
                const float* p = Bs + nj * 8 * PITCH_ + kc;
                bf[nj][0] = f2tf32(p[0]);
                bf[nj][1] = f2tf32(p[4]);
            }
#pragma unroll
            for (int mi = 0; mi < 4; mi++)
#pragma unroll
                for (int nj = 0; nj < 4; nj++)
                    mma_tf32(acc[mi][nj], af[mi][0], af[mi][1], af[mi][2],
                             af[mi][3], bf[nj][0], bf[nj][1]);
        }

        CP_WAIT0();
        __syncthreads();
    }

    // Epilogue: c0,c1 -> (row, 2tg..2tg+1); c2,c3 -> (row+8, ...)
#pragma unroll
    for (int mi = 0; mi < 4; mi++) {
        const int row0 = m0 + warpM + mi * 16 + g;
#pragma unroll
        for (int nj = 0; nj < 4; nj++) {
            const int col = n0 + warpN + nj * 8 + 2 * tg;
            float* Cp0 = C + (size_t)row0 * N + col;
            float* Cp1 = C + (size_t)(row0 + 8) * N + col;
            *(float2*)Cp0 = make_float2(acc[mi][nj][0], acc[mi][nj][1]);
            *(float2*)Cp1 = make_float2(acc[mi][nj][2], acc[mi][nj][3]);
        }
    }
}

// ---------------------------------------------------------------------------
// RoPE, in-place on q and k in [B,T,H*hd] layout. One thread per (b,t,h,i<64).
// ---------------------------------------------------------------------------
__global__ void rope_kernel(float* __restrict__ q, float* __restrict__ k)
{
    int idx = blockIdx.x * blockDim.x + threadIdx.x;
    if (idx >= B_*T_*H_*64) return;
    int i = idx & 63;
    int h = (idx >> 6) & (H_ - 1);
    int t = (idx >> 10) & (T_ - 1);
    int b = idx >> 21;

    float ex  = (float)(2*i) * (1.0f / (float)HD_);
    float inv = powf(10000.0f, -ex);
    float ang = (float)t * inv;
    float c = cosf(ang), s = sinf(ang);

    size_t base = ((size_t)(b*T_ + t)) * D_ + h*HD_ + i;
    float q1 = q[base], q2 = q[base + 64];
    q[base]      = q1*c - q2*s;
    q[base + 64] = q2*c + q1*s;
    float k1 = k[base], k2 = k[base + 64];
    k[base]      = k1*c - k2*s;
    k[base + 64] = k2*c + k1*s;
}

// ---------------------------------------------------------------------------
// Flash attention, fp32, causal (unchanged from R1 — proven correct/fast).
// ---------------------------------------------------------------------------
__device__ __forceinline__ int rot5(int r) {
    return ((r >> 2) & 7) | ((r & 3) << 3);
}
__device__ __forceinline__ int swz(int r, int c4) {
    return (r << 5) | (c4 ^ rot5(r));
}

#define ATT_SMEM_FLOATS (3*64*32*4 + 64*65)
#define ATT_SMEM_BYTES  (ATT_SMEM_FLOATS * 4)

__global__ __launch_bounds__(256)
void attn_kernel(const float* __restrict__ q, const float* __restrict__ k,
                 const float* __restrict__ v, float* __restrict__ y)
{
    extern __shared__ float smf[];
    float4* Q4 = (float4*)smf;
    float4* K4 = Q4 + 64*32;
    float4* V4 = K4 + 64*32;
    float*  Ps = (float*)(V4 + 64*32);   // [64][65]

    const int qt = blockIdx.x;
    const int h  = blockIdx.y;
    const int b  = blockIdx.z;
    const int q0 = qt * 64;
    const int tid = threadIdx.x;
    const int tm = tid >> 4;
    const int tn = tid & 15;

    const size_t headbase = ((size_t)b * T_) * D_ + (size_t)h * HD_;
    const float* qb = q + headbase + (size_t)q0 * D_;

    for (int f = tid; f < 2048; f += 256) {
        int r = f >> 5, c4 = f & 31;
        float4 t4 = *(const float4*)(qb + (size_t)r * D_ + (c4 << 2));
        t4.x *= SCALE_; t4.y *= SCALE_; t4.z *= SCALE_; t4.w *= SCALE_;
        Q4[swz(r, c4)] = t4;
    }

    float4 oA[4], oB[4];
    float mrow[4], lrow[4];
#pragma unroll
    for (int i = 0; i < 4; i++) {
        oA[i] = make_float4(0.f, 0.f, 0.f, 0.f);
        oB[i] = make_float4(0.f, 0.f, 0.f, 0.f);
        mrow[i] = -1e30f;
        lrow[i] = 0.f;
    }

    int qoff[4], qmsk[4], koff[4], kmsk[4];
#pragma unroll
    for (int i = 0; i < 4; i++) {
        int r = tm*4 + i; qoff[i] = r << 5; qmsk[i] = rot5(r);
        int c = tn*4 + i; koff[i] = c << 5; kmsk[i] = rot5(c);
    }

    for (int jt = 0; jt <= qt; jt++) {
        const int k0 = jt * 64;
        __syncthreads();
        const float* kb = k + headbase + (size_t)k0 * D_;
        const float* vb = v + headbase + (size_t)k0 * D_;
        for (int f = tid; f < 2048; f += 256) {
            int r = f >> 5, c4 = f & 31;
            K4[swz(r, c4)]   = *(const float4*)(kb + (size_t)r * D_ + (c4 << 2));
            V4[(r << 5) | c4] = *(const float4*)(vb + (size_t)r * D_ + (c4 << 2));
        }
        __syncthreads();

        float s[4][4];
#pragma unroll
        for (int i = 0; i < 4; i++)
#pragma unroll
            for (int j = 0; j < 4; j++) s[i][j] = 0.f;

#pragma unroll 2
        for (int d4 = 0; d4 < 32; d4++) {
            float4 qv[4], kv[4];
#pragma unroll
            for (int i = 0; i < 4; i++) qv[i] = Q4[qoff[i] | (d4 ^ qmsk[i])];
#pragma unroll
            for (int j = 0; j < 4; j++) kv[j] = K4[koff[j] | (d4 ^ kmsk[j])];
#pragma unroll
            for (int i = 0; i < 4; i++)
#pragma unroll
                for (int j = 0; j < 4; j++) {
                    s[i][j] = fmaf(qv[i].x, kv[j].x, s[i][j]);
                    s[i][j] = fmaf(qv[i].y, kv[j].y, s[i][j]);
                    s[i][j] = fmaf(qv[i].z, kv[j].z, s[i][j]);
                    s[i][j] = fmaf(qv[i].w, kv[j].w, s[i][j]);
                }
        }

        if (jt == qt) {
#pragma unroll
            for (int i = 0; i < 4; i++)
#pragma unroll
                for (int j = 0; j < 4; j++)
                    if (tn*4 + j > tm*4 + i) s[i][j] = -1e30f;
        }

#pragma unroll
        for (int i = 0; i < 4; i++) {
            float rm = fmaxf(fmaxf(s[i][0], s[i][1]), fmaxf(s[i][2], s[i][3]));
#pragma unroll
            for (int o = 1; o < 16; o <<= 1)
                rm = fmaxf(rm, __shfl_xor_sync(0xffffffffu, rm, o));
            float mn  = fmaxf(mrow[i], rm);
            float fct = __expf(mrow[i] - mn);
            mrow[i] = mn;
            float rs = 0.f;
#pragma unroll
            for (int j = 0; j < 4; j++) {
                float p = __expf(s[i][j] - mn);
                s[i][j] = p;
                rs += p;
            }
#pragma unroll
            for (int o = 1; o < 16; o <<= 1)
                rs += __shfl_xor_sync(0xffffffffu, rs, o);
            lrow[i] = lrow[i] * fct + rs;
            oA[i].x *= fct; oA[i].y *= fct; oA[i].z *= fct; oA[i].w *= fct;
            oB[i].x *= fct; oB[i].y *= fct; oB[i].z *= fct; oB[i].w *= fct;
            Ps[(tm*4 + i)*65 + tn*4 + 0] = s[i][0];
            Ps[(tm*4 + i)*65 + tn*4 + 1] = s[i][1];
            Ps[(tm*4 + i)*65 + tn*4 + 2] = s[i][2];
            Ps[(tm*4 + i)*65 + tn*4 + 3] = s[i][3];
        }
        __syncthreads();

#pragma unroll 2
        for (int kk = 0; kk < 64; kk++) {
            float4 va  = V4[(kk << 5) | tn];
            float4 vb4 = V4[(kk << 5) | (tn + 16)];
#pragma unroll
            for (int i = 0; i < 4; i++) {
                float p = Ps[(tm*4 + i)*65 + kk];
                oA[i].x = fmaf(p, va.x,  oA[i].x);
                oA[i].y = fmaf(p, va.y,  oA[i].y);
                oA[i].z = fmaf(p, va.z,  oA[i].z);
                oA[i].w = fmaf(p, va.w,  oA[i].w);
                oB[i].x = fmaf(p, vb4.x, oB[i].x);
                oB[i].y = fmaf(p, vb4.y, oB[i].y);
                oB[i].z = fmaf(p, vb4.z, oB[i].z);
                oB[i].w = fmaf(p, vb4.w, oB[i].w);
            }
        }
    }

    float* yb = y + headbase + (size_t)q0 * D_;
#pragma unroll
    for (int i = 0; i < 4; i++) {
        float inv = 1.0f / lrow[i];
        float4 ra = oA[i]; ra.x *= inv; ra.y *= inv; ra.z *= inv; ra.w *= inv;
        float4 rb = oB[i]; rb.x *= inv; rb.y *= inv; rb.z *= inv; rb.w *= inv;
        *(float4*)(yb + (size_t)(tm*4 + i) * D_ + (tn << 2))        = ra;
        *(float4*)(yb + (size_t)(tm*4 + i) * D_ + ((tn + 16) << 2)) = rb;
    }
}

// ---------------------------------------------------------------------------
extern "C" void kernel_launch(void* const* d_in, const int* in_sizes, int n_in,
                              void* d_out, int out_size)
{
    const float* x  = (const float*)d_in[0];
    const float* wq = (const float*)d_in[1];
    const float* wk = (const float*)d_in[2];
    const float* wv = (const float*)d_in[3];
    const float* wo = (const float*)d_in[4];
    float* out = (float*)d_out;

    float *q, *k, *v, *y;
    cudaGetSymbolAddress((void**)&q, g_q);
    cudaGetSymbolAddress((void**)&k, g_k);
    cudaGetSymbolAddress((void**)&v, g_v);
    cudaGetSymbolAddress((void**)&y, g_y);

    cudaFuncSetAttribute(mma_gemm_nt,
                         cudaFuncAttributeMaxDynamicSharedMemorySize,
                         GEMM_SMEM_BYTES);
    cudaFuncSetAttribute(attn_kernel,
                         cudaFuncAttributeMaxDynamicSharedMemorySize,
                         ATT_SMEM_BYTES);

    dim3 gproj(D_ / 128, NTOK_ / 128);   // (16, 64)
    mma_gemm_nt<<<gproj, 256, GEMM_SMEM_BYTES>>>(x, wq, q, NTOK_, D_, D_);
    mma_gemm_nt<<<gproj, 256, GEMM_SMEM_BYTES>>>(x, wk, k, NTOK_, D_, D_);
    mma_gemm_nt<<<gproj, 256, GEMM_SMEM_BYTES>>>(x, wv, v, NTOK_, D_, D_);

    int nrope = B_*T_*H_*64;
    rope_kernel<<<(nrope + 255) / 256, 256>>>(q, k);

    dim3 gattn(T_ / 64, H_, B_);         // (32, 16, 4)
    attn_kernel<<<gattn, 256, ATT_SMEM_BYTES>>>(q, k, v, y);

    mma_gemm_nt<<<gproj, 256, GEMM_SMEM_BYTES>>>(y, wo, out, NTOK_, D_, D_);
}

// round 4
// speedup vs baseline: 3.2452x; 1.5696x over previous
#include <cuda_runtime.h>
#include <math.h>
#include <stdint.h>

// Problem constants (fixed shapes)
#define B_  4
#define T_  2048
#define D_  2048
#define H_  16
#define HD_ 128
#define NTOK_ (B_*T_)                 // 8192
#define SCALE_ 0.08838834764831845f   // 1/sqrt(128)

// Scratch (allocation-free rule: __device__ globals). 4 x 64MB.
__device__ float g_q[NTOK_*(size_t)D_];
__device__ float g_k[NTOK_*(size_t)D_];
__device__ float g_v[NTOK_*(size_t)D_];
__device__ float g_y[NTOK_*(size_t)D_];

// ===========================================================================
// Helpers
// ===========================================================================
__device__ __forceinline__ uint32_t smem_u32(const void* p) {
    uint32_t a;
    asm("{ .reg .u64 t; cvta.to.shared.u64 t, %1; cvt.u32.u64 %0, t; }"
        : "=r"(a) : "l"(p));
    return a;
}
__device__ __forceinline__ void cp16(uint32_t saddr, const void* gaddr) {
    asm volatile("cp.async.cg.shared.global [%0], [%1], 16;"
                 :: "r"(saddr), "l"(gaddr) : "memory");
}
#define CP_COMMIT() asm volatile("cp.async.commit_group;" ::: "memory")
#define CP_WAIT0()  asm volatile("cp.async.wait_group 0;" ::: "memory")
#define CP_WAIT1()  asm volatile("cp.async.wait_group 1;" ::: "memory")

__device__ __forceinline__ uint32_t f2tf32(float f) {
    uint32_t u;
    asm("cvt.rna.tf32.f32 %0, %1;" : "=r"(u) : "f"(f));
    return u;
}
__device__ __forceinline__ void mma_tf32(float c[4], uint32_t a0, uint32_t a1,
                                         uint32_t a2, uint32_t a3,
                                         uint32_t b0, uint32_t b1) {
    asm volatile(
        "mma.sync.aligned.m16n8k8.row.col.f32.tf32.tf32.f32 "
        "{%0,%1,%2,%3}, {%4,%5,%6,%7}, {%8,%9}, {%0,%1,%2,%3};"
        : "+f"(c[0]), "+f"(c[1]), "+f"(c[2]), "+f"(c[3])
        : "r"(a0), "r"(a1), "r"(a2), "r"(a3), "r"(b0), "r"(b1));
}

// ===========================================================================
// tf32 mma.sync GEMM (unchanged from R3): C[M,N] = A[M,K] @ W[N,K]^T.
// ===========================================================================
#define BK_      32
#define PITCH_   36
#define STAGE_F  (128 * PITCH_)
#define GEMM_SMEM_BYTES (4 * STAGE_F * 4)

__global__ __launch_bounds__(256)
void mma_gemm_nt(const float* __restrict__ A, const float* __restrict__ W,
                 float* __restrict__ C, int M, int N, int K)
{
    extern __shared__ float smf[];
    float* Asm = smf;
    float* Bsm = smf + 2 * STAGE_F;

    const int tid  = threadIdx.x;
    const int wid  = tid >> 5;
    const int lane = tid & 31;
    const int g    = lane >> 2;
    const int tg   = lane & 3;
    const int warpM = (wid & 1) * 64;
    const int warpN = (wid >> 1) * 32;
    const int m0 = blockIdx.y * 128;
    const int n0 = blockIdx.x * 128;

    const int lr = tid >> 3;
    const int lc4 = tid & 7;
    const uint32_t sA_base = smem_u32(Asm);
    const uint32_t sB_base = smem_u32(Bsm);

    float acc[4][4][4];
#pragma unroll
    for (int i = 0; i < 4; i++)
#pragma unroll
        for (int j = 0; j < 4; j++)
#pragma unroll
            for (int c = 0; c < 4; c++) acc[i][j][c] = 0.f;

    const int niter = K / BK_;

    auto issue = [&](int ck, int s) {
        const float* Ab = A + (size_t)m0 * K + ck * BK_;
        const float* Wb = W + (size_t)n0 * K + ck * BK_;
        const uint32_t so = (uint32_t)(s * STAGE_F * 4);
#pragma unroll
        for (int u = 0; u < 4; u++) {
            int r = lr + u * 32;
            cp16(sA_base + so + (uint32_t)(r * PITCH_ + lc4 * 4) * 4,
                 Ab + (size_t)r * K + lc4 * 4);
        }
#pragma unroll
        for (int u = 0; u < 4; u++) {
            int r = lr + u * 32;
            cp16(sB_base + so + (uint32_t)(r * PITCH_ + lc4 * 4) * 4,
                 Wb + (size_t)r * K + lc4 * 4);
        }
    };

    issue(0, 0);
    CP_COMMIT();
    CP_WAIT0();
    __syncthreads();

    for (int it = 0; it < niter; it++) {
        const int cur = it & 1;
        if (it + 1 < niter) {
            issue(it + 1, cur ^ 1);
            CP_COMMIT();
        }

        const float* As = Asm + cur * STAGE_F + (warpM + g) * PITCH_;
        const float* Bs = Bsm + cur * STAGE_F + (warpN + g) * PITCH_;
#pragma unroll
        for (int ks = 0; ks < 4; ks++) {
            const int kc = ks * 8 + tg;
            uint32_t af[4][4], bf[4][2];
#pragma unroll
            for (int mi = 0; mi < 4; mi++) {
                const float* p = As + mi * 16 * PITCH_ + kc;
                af[mi][0] = f2tf32(p[0]);
                af[mi][1] = f2tf32(p[8 * PITCH_]);
                af[mi][2] = f2tf32(p[4]);
                af[mi][3] = f2tf32(p[8 * PITCH_ + 4]);
            }
#pragma unroll
            for (int nj = 0; nj < 4; nj++) {
                const float* p = Bs + nj * 8 * PITCH_ + kc;
                bf[nj][0] = f2tf32(p[0]);
                bf[nj][1] = f2tf32(p[4]);
            }
#pragma unroll
            for (int mi = 0; mi < 4; mi++)
#pragma unroll
                for (int nj = 0; nj < 4; nj++)
                    mma_tf32(acc[mi][nj], af[mi][0], af[mi][1], af[mi][2],
                             af[mi][3], bf[nj][0], bf[nj][1]);
        }

        CP_WAIT0();
        __syncthreads();
    }

#pragma unroll
    for (int mi = 0; mi < 4; mi++) {
        const int row0 = m0 + warpM + mi * 16 + g;
#pragma unroll
        for (int nj = 0; nj < 4; nj++) {
            const int col = n0 + warpN + nj * 8 + 2 * tg;
            float* Cp0 = C + (size_t)row0 * N + col;
            float* Cp1 = C + (size_t)(row0 + 8) * N + col;
            *(float2*)Cp0 = make_float2(acc[mi][nj][0], acc[mi][nj][1]);
            *(float2*)Cp1 = make_float2(acc[mi][nj][2], acc[mi][nj][3]);
        }
    }
}

// ---------------------------------------------------------------------------
// RoPE, in-place on q and k (unchanged).
// ---------------------------------------------------------------------------
__global__ void rope_kernel(float* __restrict__ q, float* __restrict__ k)
{
    int idx = blockIdx.x * blockDim.x + threadIdx.x;
    if (idx >= B_*T_*H_*64) return;
    int i = idx & 63;
    int h = (idx >> 6) & (H_ - 1);
    int t = (idx >> 10) & (T_ - 1);
    int b = idx >> 21;

    float ex  = (float)(2*i) * (1.0f / (float)HD_);
    float inv = powf(10000.0f, -ex);
    float ang = (float)t * inv;
    float c = cosf(ang), s = sinf(ang);

    size_t base = ((size_t)(b*T_ + t)) * D_ + h*HD_ + i;
    float q1 = q[base], q2 = q[base + 64];
    q[base]      = q1*c - q2*s;
    q[base + 64] = q2*c + q1*s;
    float k1 = k[base], k2 = k[base + 64];
    k[base]      = k1*c - k2*s;
    k[base + 64] = k2*c + k1*s;
}

// ===========================================================================
// Tensor-core flash attention (tf32 mma.sync), causal.
// CTA: 64 q-rows, 256 threads (8 warps). Warp w: m-tile mt=w&3 (16 rows),
// half nh=w>>2 (S: 32 cols; PV: 64 out cols).
// Q tf32 smem pitch 132; K fp32 pitch 132; V fp32 pitch 136; P tf32 pitch 68.
// K/V double-buffered via cp.async (one group per tile).
// ===========================================================================
#define AQP 132
#define AKP 132
#define AVP 136
#define APP 68
#define AQ_F (64*AQP)
#define AK_F (64*AKP)
#define AV_F (64*AVP)
#define ATTN_SMEM_BYTES ((AQ_F + 2*AK_F + 2*AV_F + 64*APP + 256) * 4)

__global__ __launch_bounds__(256)
void attn_mma(const float* __restrict__ q, const float* __restrict__ k,
              const float* __restrict__ v, float* __restrict__ y)
{
    extern __shared__ float smf[];
    uint32_t* Qs   = (uint32_t*)smf;                 // [64][132] tf32
    float*    Ks   = smf + AQ_F;                     // [2][64][132] fp32
    float*    Vs   = Ks + 2*AK_F;                    // [2][64][136] fp32
    uint32_t* Ps   = (uint32_t*)(Vs + 2*AV_F);       // [64][68] tf32
    float*    pmax2 = (float*)(Ps + 64*APP);         // [2][64]
    float*    psum2 = pmax2 + 128;                   // [2][64]

    const int qt = blockIdx.x;
    const int h  = blockIdx.y;
    const int b  = blockIdx.z;
    const int q0 = qt * 64;
    const int tid  = threadIdx.x;
    const int wid  = tid >> 5;
    const int lane = tid & 31;
    const int g    = lane >> 2;
    const int tg   = lane & 3;
    const int mt   = wid & 3;
    const int nh   = wid >> 2;

    const size_t headbase = ((size_t)b * T_) * D_ + (size_t)h * HD_;
    const float* qb = q + headbase + (size_t)q0 * D_;
    const uint32_t sK = smem_u32(Ks);
    const uint32_t sV = smem_u32(Vs);

    // Loader slots: f = tid + u*256; r = f>>5 (0..63), c4 = f&31 (16B chunk)
    const int lr  = tid >> 5;
    const int lc4 = tid & 31;

    // Q load: fp32 -> *SCALE -> tf32
#pragma unroll
    for (int u = 0; u < 8; u++) {
        int r = lr + u * 8;
        float4 t4 = *(const float4*)(qb + (size_t)r * D_ + lc4 * 4);
        uint4 u4;
        u4.x = f2tf32(t4.x * SCALE_); u4.y = f2tf32(t4.y * SCALE_);
        u4.z = f2tf32(t4.z * SCALE_); u4.w = f2tf32(t4.w * SCALE_);
        *(uint4*)&Qs[r * AQP + lc4 * 4] = u4;
    }

    auto issueKV = [&](int jt, int s) {
        const float* kb = k + headbase + (size_t)(jt * 64) * D_;
        const float* vb = v + headbase + (size_t)(jt * 64) * D_;
        const uint32_t koff = (uint32_t)(s * AK_F * 4);
        const uint32_t voff = (uint32_t)(s * AV_F * 4);
#pragma unroll
        for (int u = 0; u < 8; u++) {
            int r = lr + u * 8;
            cp16(sK + koff + (uint32_t)(r * AKP + lc4 * 4) * 4,
                 kb + (size_t)r * D_ + lc4 * 4);
        }
#pragma unroll
        for (int u = 0; u < 8; u++) {
            int r = lr + u * 8;
            cp16(sV + voff + (uint32_t)(r * AVP + lc4 * 4) * 4,
                 vb + (size_t)r * D_ + lc4 * 4);
        }
        CP_COMMIT();
    };

    issueKV(0, 0);

    float oc[8][4];
#pragma unroll
    for (int nj = 0; nj < 8; nj++)
#pragma unroll
        for (int c = 0; c < 4; c++) oc[nj][c] = 0.f;
    float m0r = -1e30f, m1r = -1e30f, l0r = 0.f, l1r = 0.f;

    const int row0 = mt * 16 + g;
    const int row1 = row0 + 8;
    const uint32_t* qrow0 = Qs + row0 * AQP;
    const uint32_t* qrow1 = Qs + row1 * AQP;
    uint32_t* prow0 = Ps + row0 * APP;
    uint32_t* prow1 = Ps + row1 * APP;

    for (int jt = 0; jt <= qt; jt++) {
        const int cur = jt & 1;
        if (jt < qt) issueKV(jt + 1, cur ^ 1);
        if (jt < qt) { CP_WAIT1(); } else { CP_WAIT0(); }
        __syncthreads();

        const float* Kst = Ks + cur * AK_F;
        const float* Vst = Vs + cur * AV_F;

        // ---- S = Q @ K^T (warp: 16 x 32) ----
        float sc[4][4];
#pragma unroll
        for (int nj = 0; nj < 4; nj++)
#pragma unroll
            for (int c = 0; c < 4; c++) sc[nj][c] = 0.f;

        const float* kb0 = Kst + (nh * 32 + g) * AKP;
#pragma unroll
        for (int ks = 0; ks < 16; ks++) {
            const int kc = ks * 8 + tg;
            uint32_t a0 = qrow0[kc], a1 = qrow1[kc];
            uint32_t a2 = qrow0[kc + 4], a3 = qrow1[kc + 4];
#pragma unroll
            for (int nj = 0; nj < 4; nj++) {
                const float* p = kb0 + nj * 8 * AKP + kc;
                uint32_t b0v = f2tf32(p[0]);
                uint32_t b1v = f2tf32(p[4]);
                mma_tf32(sc[nj], a0, a1, a2, a3, b0v, b1v);
            }
        }

        // ---- causal mask on diagonal tile ----
        if (jt == qt) {
#pragma unroll
            for (int nj = 0; nj < 4; nj++) {
                int colb = nh * 32 + nj * 8 + 2 * tg;
                if (colb     > row0) sc[nj][0] = -1e30f;
                if (colb + 1 > row0) sc[nj][1] = -1e30f;
                if (colb     > row1) sc[nj][2] = -1e30f;
                if (colb + 1 > row1) sc[nj][3] = -1e30f;
            }
        }

        // ---- online softmax ----
        float pm0 = -1e30f, pm1 = -1e30f;
#pragma unroll
        for (int nj = 0; nj < 4; nj++) {
            pm0 = fmaxf(pm0, fmaxf(sc[nj][0], sc[nj][1]));
            pm1 = fmaxf(pm1, fmaxf(sc[nj][2], sc[nj][3]));
        }
        pm0 = fmaxf(pm0, __shfl_xor_sync(0xffffffffu, pm0, 1));
        pm0 = fmaxf(pm0, __shfl_xor_sync(0xffffffffu, pm0, 2));
        pm1 = fmaxf(pm1, __shfl_xor_sync(0xffffffffu, pm1, 1));
        pm1 = fmaxf(pm1, __shfl_xor_sync(0xffffffffu, pm1, 2));
        if (tg == 0) {
            pmax2[nh * 64 + row0] = pm0;
            pmax2[nh * 64 + row1] = pm1;
        }
        __syncthreads();
        float mt0 = fmaxf(pmax2[row0], pmax2[64 + row0]);
        float mt1 = fmaxf(pmax2[row1], pmax2[64 + row1]);
        float mn0 = fmaxf(m0r, mt0), mn1 = fmaxf(m1r, mt1);
        float fct0 = __expf(m0r - mn0), fct1 = __expf(m1r - mn1);
        m0r = mn0; m1r = mn1;

        float ps0 = 0.f, ps1 = 0.f;
#pragma unroll
        for (int nj = 0; nj < 4; nj++) {
            float p00 = __expf(sc[nj][0] - mn0);
            float p01 = __expf(sc[nj][1] - mn0);
            float p10 = __expf(sc[nj][2] - mn1);
            float p11 = __expf(sc[nj][3] - mn1);
            ps0 += p00 + p01;
            ps1 += p10 + p11;
            int colb = nh * 32 + nj * 8 + 2 * tg;
            *(uint2*)&prow0[colb] = make_uint2(f2tf32(p00), f2tf32(p01));
            *(uint2*)&prow1[colb] = make_uint2(f2tf32(p10), f2tf32(p11));
        }
        ps0 += __shfl_xor_sync(0xffffffffu, ps0, 1);
        ps0 += __shfl_xor_sync(0xffffffffu, ps0, 2);
        ps1 += __shfl_xor_sync(0xffffffffu, ps1, 1);
        ps1 += __shfl_xor_sync(0xffffffffu, ps1, 2);
        if (tg == 0) {
            psum2[nh * 64 + row0] = ps0;
            psum2[nh * 64 + row1] = ps1;
        }
        __syncthreads();
        l0r = l0r * fct0 + psum2[row0] + psum2[64 + row0];
        l1r = l1r * fct1 + psum2[row1] + psum2[64 + row1];

        // rescale O
#pragma unroll
        for (int nj = 0; nj < 8; nj++) {
            oc[nj][0] *= fct0; oc[nj][1] *= fct0;
            oc[nj][2] *= fct1; oc[nj][3] *= fct1;
        }

        // ---- O += P @ V (warp: 16 rows x 64 cols) ----
        const float* vb0 = Vst + nh * 64 + g;
#pragma unroll
        for (int ks = 0; ks < 8; ks++) {
            const int kc = ks * 8 + tg;
            uint32_t a0 = prow0[kc], a1 = prow1[kc];
            uint32_t a2 = prow0[kc + 4], a3 = prow1[kc + 4];
            const float* vk0 = vb0 + kc * AVP;
            const float* vk1 = vb0 + (kc + 4) * AVP;
#pragma unroll
            for (int nj = 0; nj < 8; nj++) {
                uint32_t b0v = f2tf32(vk0[nj * 8]);
                uint32_t b1v = f2tf32(vk1[nj * 8]);
                mma_tf32(oc[nj], a0, a1, a2, a3, b0v, b1v);
            }
        }
    }

    // ---- epilogue: O /= l, write ----
    float inv0 = 1.0f / l0r, inv1 = 1.0f / l1r;
    float* yb = y + headbase + (size_t)q0 * D_;
#pragma unroll
    for (int nj = 0; nj < 8; nj++) {
        int col = nh * 64 + nj * 8 + 2 * tg;
        *(float2*)(yb + (size_t)(row0) * D_ + col) =
            make_float2(oc[nj][0] * inv0, oc[nj][1] * inv0);
        *(float2*)(yb + (size_t)(row1) * D_ + col) =
            make_float2(oc[nj][2] * inv1, oc[nj][3] * inv1);
    }
}

// ---------------------------------------------------------------------------
extern "C" void kernel_launch(void* const* d_in, const int* in_sizes, int n_in,
                              void* d_out, int out_size)
{
    const float* x  = (const float*)d_in[0];
    const float* wq = (const float*)d_in[1];
    const float* wk = (const float*)d_in[2];
    const float* wv = (const float*)d_in[3];
    const float* wo = (const float*)d_in[4];
    float* out = (float*)d_out;

    float *q, *k, *v, *y;
    cudaGetSymbolAddress((void**)&q, g_q);
    cudaGetSymbolAddress((void**)&k, g_k);
    cudaGetSymbolAddress((void**)&v, g_v);
    cudaGetSymbolAddress((void**)&y, g_y);

    cudaFuncSetAttribute(mma_gemm_nt,
                         cudaFuncAttributeMaxDynamicSharedMemorySize,
                         GEMM_SMEM_BYTES);
    cudaFuncSetAttribute(attn_mma,
                         cudaFuncAttributeMaxDynamicSharedMemorySize,
                         ATTN_SMEM_BYTES);

    dim3 gproj(D_ / 128, NTOK_ / 128);   // (16, 64)
    mma_gemm_nt<<<gproj, 256, GEMM_SMEM_BYTES>>>(x, wq, q, NTOK_, D_, D_);
    mma_gemm_nt<<<gproj, 256, GEMM_SMEM_BYTES>>>(x, wk, k, NTOK_, D_, D_);
    mma_gemm_nt<<<gproj, 256, GEMM_SMEM_BYTES>>>(x, wv, v, NTOK_, D_, D_);

    int nrope = B_*T_*H_*64;
    rope_kernel<<<(nrope + 255) / 256, 256>>>(q, k);

    dim3 gattn(T_ / 64, H_, B_);         // (32, 16, 4)
    attn_mma<<<gattn, 256, ATTN_SMEM_BYTES>>>(q, k, v, y);

    mma_gemm_nt<<<gproj, 256, GEMM_SMEM_BYTES>>>(y, wo, out, NTOK_, D_, D_);
}